// round 15
// baseline (speedup 1.0000x reference)
#include <cuda_runtime.h>

// out[b][j] = x[b][(j - s_b) mod T]
// B = 256 rows, T = 100000 (divisible by 4). Pure HBM-bound stream.
// Writes: float4-aligned STG.128. Reads: 4 contiguous LDG.32 (warp-coalesced,
// just offset by s within the row — full sector utilization either way).

__global__ void ShiftAugmentation_kernel(const float* __restrict__ x,
                                         const int* __restrict__ shifts,
                                         float4* __restrict__ out4,
                                         int T, int T4) {
    const int b  = blockIdx.y;
    const int j4 = blockIdx.x * blockDim.x + threadIdx.x;
    if (j4 >= T4) return;

    // Normalize shift into [0, T). Reference uses mod T; inputs are [0,1000)
    // but be robust anyway.
    int s = shifts[b] % T;
    if (s < 0) s += T;

    const long long base = (long long)b * (long long)T;
    const float* __restrict__ row = x + base;

    const int j = j4 << 2;

    // src_k = j + k - s; since 0 <= s < T and 0 <= j+k < T, one wrap-add fixes it.
    int s0 = j + 0 - s; if (s0 < 0) s0 += T;
    int s1 = j + 1 - s; if (s1 < 0) s1 += T;
    int s2 = j + 2 - s; if (s2 < 0) s2 += T;
    int s3 = j + 3 - s; if (s3 < 0) s3 += T;

    float4 v;
    v.x = __ldg(row + s0);
    v.y = __ldg(row + s1);
    v.z = __ldg(row + s2);
    v.w = __ldg(row + s3);

    out4[(long long)b * (long long)T4 + j4] = v;
}

// Tail kernel for T % 4 != 0 (not needed for T=100000, but keep it general).
__global__ void ShiftAugmentation_tail(const float* __restrict__ x,
                                       const int* __restrict__ shifts,
                                       float* __restrict__ out,
                                       int T, int jstart) {
    const int b = blockIdx.y;
    const int j = jstart + blockIdx.x * blockDim.x + threadIdx.x;
    if (j >= T) return;
    int s = shifts[b] % T;
    if (s < 0) s += T;
    int src = j - s; if (src < 0) src += T;
    const long long base = (long long)b * (long long)T;
    out[base + j] = x[base + src];
}

extern "C" void kernel_launch(void* const* d_in, const int* in_sizes, int n_in,
                              void* d_out, int out_size) {
    const float* x      = (const float*)d_in[0];
    const int*   shifts = (const int*)d_in[1];
    float*       out    = (float*)d_out;

    const int B = in_sizes[1];           // 256
    const int T = in_sizes[0] / B;       // 100000
    const int T4 = T >> 2;               // vectorizable prefix (T divisible by 4 here)

    const int threads = 256;
    dim3 grid((T4 + threads - 1) / threads, B);
    ShiftAugmentation_kernel<<<grid, threads>>>(x, shifts, (float4*)out, T, T4);

    const int rem = T - (T4 << 2);
    if (rem > 0) {
        dim3 g2((rem + threads - 1) / threads, B);
        ShiftAugmentation_tail<<<g2, threads>>>(x, shifts, out, T, T4 << 2);
    }
}

// round 16
// speedup vs baseline: 1.0033x; 1.0033x over previous
#include <cuda_runtime.h>

// out[b][j] = x[b][(j - s_b) mod T]
// B = 256 rows, T = 100000 (divisible by 4). Pure HBM-bound stream.
// Writes: float4-aligned STG.128. Reads: 4 contiguous LDG.32 (warp-coalesced,
// just offset by s within the row — full sector utilization either way).

__global__ void ShiftAugmentation_kernel(const float* __restrict__ x,
                                         const int* __restrict__ shifts,
                                         float4* __restrict__ out4,
                                         int T, int T4) {
    const int b  = blockIdx.y;
    const int j4 = blockIdx.x * blockDim.x + threadIdx.x;
    if (j4 >= T4) return;

    // Normalize shift into [0, T). Reference uses mod T; inputs are [0,1000)
    // but be robust anyway.
    int s = shifts[b] % T;
    if (s < 0) s += T;

    const long long base = (long long)b * (long long)T;
    const float* __restrict__ row = x + base;

    const int j = j4 << 2;

    // src_k = j + k - s; since 0 <= s < T and 0 <= j+k < T, one wrap-add fixes it.
    int s0 = j + 0 - s; if (s0 < 0) s0 += T;
    int s1 = j + 1 - s; if (s1 < 0) s1 += T;
    int s2 = j + 2 - s; if (s2 < 0) s2 += T;
    int s3 = j + 3 - s; if (s3 < 0) s3 += T;

    float4 v;
    v.x = __ldg(row + s0);
    v.y = __ldg(row + s1);
    v.z = __ldg(row + s2);
    v.w = __ldg(row + s3);

    out4[(long long)b * (long long)T4 + j4] = v;
}

// Tail kernel for T % 4 != 0 (not needed for T=100000, but keep it general).
__global__ void ShiftAugmentation_tail(const float* __restrict__ x,
                                       const int* __restrict__ shifts,
                                       float* __restrict__ out,
                                       int T, int jstart) {
    const int b = blockIdx.y;
    const int j = jstart + blockIdx.x * blockDim.x + threadIdx.x;
    if (j >= T) return;
    int s = shifts[b] % T;
    if (s < 0) s += T;
    int src = j - s; if (src < 0) src += T;
    const long long base = (long long)b * (long long)T;
    out[base + j] = x[base + src];
}

extern "C" void kernel_launch(void* const* d_in, const int* in_sizes, int n_in,
                              void* d_out, int out_size) {
    const float* x      = (const float*)d_in[0];
    const int*   shifts = (const int*)d_in[1];
    float*       out    = (float*)d_out;

    const int B = in_sizes[1];           // 256
    const int T = in_sizes[0] / B;       // 100000
    const int T4 = T >> 2;               // vectorizable prefix (T divisible by 4 here)

    const int threads = 256;
    dim3 grid((T4 + threads - 1) / threads, B);
    ShiftAugmentation_kernel<<<grid, threads>>>(x, shifts, (float4*)out, T, T4);

    const int rem = T - (T4 << 2);
    if (rem > 0) {
        dim3 g2((rem + threads - 1) / threads, B);
        ShiftAugmentation_tail<<<g2, threads>>>(x, shifts, out, T, T4 << 2);
    }
}